// round 9
// baseline (speedup 1.0000x reference)
#include <cuda_runtime.h>

#define NEG_SLOPE 0.2f

// x: [B=8, C=256, H=128, W=128] f32. row = b*C+c.
static constexpr int NROWS = 2048;
static constexpr int ROW_ELEMS = 16384;          // H*W
static constexpr int ROW_VEC4 = ROW_ELEMS / 4;   // 4096
static constexpr int HALF_VEC4 = ROW_VEC4 / 2;   // 2048
static constexpr int C = 256;
static constexpr int CS = 16;

static constexpr int GROUP_ROWS = 256;             // 1 batch = 16.75 MB
static constexpr int NGROUPS = NROWS / GROUP_ROWS; // 8

static constexpr int SCALE_CTAS = 2 * GROUP_ROWS;  // 512 half-row scale CTAs
static constexpr int GAP_CTAS = GROUP_ROWS;        // 256 gap CTAs
static constexpr int GRID = SCALE_CTAS + GAP_CTAS; // 768

__device__ float g_y[NROWS];   // pooled means

struct f8 { float a0,a1,a2,a3,a4,a5,a6,a7; };

// 32-byte load with L2 evict_last (sm_103 requires v4.b64 width for the hint).
// Pins the freshly-pooled group in L2 until its scale pass next step.
__device__ __forceinline__ f8 ldg_evict_last_32B(const void* p) {
    unsigned long long d0, d1, d2, d3;
    asm("ld.global.L2::evict_last.v4.b64 {%0,%1,%2,%3}, [%4];"
        : "=l"(d0), "=l"(d1), "=l"(d2), "=l"(d3)
        : "l"(p));
    f8 r;
    r.a0 = __uint_as_float((unsigned)(d0));
    r.a1 = __uint_as_float((unsigned)(d0 >> 32));
    r.a2 = __uint_as_float((unsigned)(d1));
    r.a3 = __uint_as_float((unsigned)(d1 >> 32));
    r.a4 = __uint_as_float((unsigned)(d2));
    r.a5 = __uint_as_float((unsigned)(d2 >> 32));
    r.a6 = __uint_as_float((unsigned)(d3));
    r.a7 = __uint_as_float((unsigned)(d3 >> 32));
    return r;
}

// ---------------------------------------------------------------------------
// Pipelined step kernel (1-batch groups):
//   bid in [0, 512):   scale HALF-row of group (step-1): 32KB rd(L2) + 32KB wr
//   bid in [512, 768): gap one row of group step: 64KB rd, installed evict_last
// Kernel-boundary ordering makes g_y safe; no grid sync, no atomics.
// ---------------------------------------------------------------------------
__global__ __launch_bounds__(256) void pipe_kernel(const float* __restrict__ x,
                                                   const float* __restrict__ w1,
                                                   const float* __restrict__ b1,
                                                   const float* __restrict__ w2,
                                                   const float* __restrict__ b2,
                                                   float* __restrict__ out,
                                                   int step) {
    const int tid = threadIdx.x;
    const int bid = blockIdx.x;

    if (bid >= SCALE_CTAS) {
        // ---------------- GAP role: pool one row of group `step` ----------------
        if (step >= NGROUPS) return;
        const int row = step * GROUP_ROWS + (bid - SCALE_CTAS);
        const char* __restrict__ xr =
            reinterpret_cast<const char*>(x) + (size_t)row * ROW_ELEMS * 4;

        float s = 0.f;
#pragma unroll
        for (int i = 0; i < ROW_ELEMS / 8 / 256; i++) {   // 8 iters of 32B
            f8 v = ldg_evict_last_32B(xr + (size_t)(tid + i * 256) * 32);
            s += ((v.a0 + v.a1) + (v.a2 + v.a3)) + ((v.a4 + v.a5) + (v.a6 + v.a7));
        }
#pragma unroll
        for (int off = 16; off > 0; off >>= 1)
            s += __shfl_xor_sync(0xFFFFFFFF, s, off);

        __shared__ float warp_sums[8];
        if ((tid & 31) == 0) warp_sums[tid >> 5] = s;
        __syncthreads();
        if (tid == 0) {
            float tot = 0.f;
#pragma unroll
            for (int w = 0; w < 8; w++) tot += warp_sums[w];
            g_y[row] = tot * (1.0f / ROW_ELEMS);
        }
        return;
    }

    // ------------- SCALE role: gate + scale half a row of group `step-1` -------------
    if (step < 1) return;
    const int row = (step - 1) * GROUP_ROWS + (bid >> 1);
    const int half = bid & 1;
    const int b = row / C;
    const int c = row % C;

    // Inline FC (redundant per CTA; FMA pipe is otherwise idle):
    __shared__ float sh_y1[CS];
    __shared__ float sh_gate;
    {
        const int s_idx = tid >> 4;   // 0..15
        const int cc = tid & 15;      // 0..15
        const float* __restrict__ yb = g_y + b * C;
        const float* __restrict__ wrow = w1 + s_idx * C;
        float part = 0.f;
#pragma unroll
        for (int k = 0; k < C / 16; k++) {
            const int cidx = cc + k * 16;
            part += wrow[cidx] * yb[cidx];
        }
#pragma unroll
        for (int off = 8; off > 0; off >>= 1)
            part += __shfl_down_sync(0xFFFFFFFF, part, off, 16);
        if (cc == 0) {
            part += b1[s_idx];
            sh_y1[s_idx] = (part >= 0.f) ? part : NEG_SLOPE * part;
        }
    }
    __syncthreads();
    if (tid == 0) {
        const float* __restrict__ w2row = w2 + c * CS;
        float acc = b2[c];
#pragma unroll
        for (int s = 0; s < CS; s++) acc += w2row[s] * sh_y1[s];
        sh_gate = 1.0f / (1.0f + __expf(-acc));
    }
    __syncthreads();
    const float g = sh_gate;

    const size_t base = (size_t)row * ROW_VEC4 + (size_t)half * HALF_VEC4;
    const float4* __restrict__ xr = reinterpret_cast<const float4*>(x) + base;
    float4* __restrict__ orow = reinterpret_cast<float4*>(out) + base;
#pragma unroll
    for (int i = 0; i < HALF_VEC4 / 256; i++) {   // 8 iterations
        float4 v = xr[tid + i * 256];   // L2 hit: pinned by previous step's gap
        v.x *= g; v.y *= g; v.z *= g; v.w *= g;
        orow[tid + i * 256] = v;
    }
}

extern "C" void kernel_launch(void* const* d_in, const int* in_sizes, int n_in,
                              void* d_out, int out_size) {
    const float* x  = (const float*)d_in[0];
    const float* w1 = (const float*)d_in[1];
    const float* b1 = (const float*)d_in[2];
    const float* w2 = (const float*)d_in[3];
    const float* b2 = (const float*)d_in[4];
    float* out = (float*)d_out;

    // steps: 0 = gap(g0); 1..7 = scale(g-1)+gap(g); 8 = scale(g7)
    for (int step = 0; step <= NGROUPS; step++) {
        pipe_kernel<<<GRID, 256>>>(x, w1, b1, w2, b2, out, step);
    }
}